// round 1
// baseline (speedup 1.0000x reference)
#include <cuda_runtime.h>

#define RES    64
#define DIM    256
#define HEADS  8
#define HD     32
#define WIN    512
#define NWB    32                       // B(4) * (W/W_SP = 8) windows
#define SCALE  0.17677669529663687f     // 32^-0.5

// LePE scratch: [n][t][c] = [32][512][256] fp32 = 16 MB (device global, no alloc)
__device__ float g_lepe[(size_t)NWB * WIN * DIM];

// ---------------------------------------------------------------------------
// Kernel 1: depthwise 3x3 SAME conv on per-window v images -> g_lepe[n][t][c]
//   vimg[n, c, hs, ws] = qkv[2, b, hs*64 + w2*8 + ws, c],  n = b*8 + w2
// ---------------------------------------------------------------------------
__global__ void lepe_kernel(const float* __restrict__ qkv,
                            const float* __restrict__ cw,
                            const float* __restrict__ cb) {
    int c  = threadIdx.x;            // 0..255 (channel)
    int nt = blockIdx.x;             // 0..NWB*WIN-1
    int n  = nt >> 9, t = nt & 511;
    int b  = n >> 3,  w2 = n & 7;
    int hs = t >> 3,  ws = t & 7;
    const float* v = qkv + ((size_t)(2 * 4 + b)) * 4096 * 256;

    float acc = cb[c];
    #pragma unroll
    for (int dy = -1; dy <= 1; dy++) {
        int ys = hs + dy;
        if ((unsigned)ys >= 64u) continue;     // zero pad (per-window image!)
        #pragma unroll
        for (int dx = -1; dx <= 1; dx++) {
            int xs = ws + dx;
            if ((unsigned)xs >= 8u) continue;
            int l = ys * 64 + w2 * 8 + xs;
            acc += v[(size_t)l * 256 + c] * cw[c * 9 + (dy + 1) * 3 + (dx + 1)];
        }
    }
    g_lepe[((size_t)nt) * 256 + c] = acc;
}

// ---------------------------------------------------------------------------
// Kernel 2: S = scale * Q K^T  (per window,head), row softmax, write attn.
// Grid: x = 16 row-blocks of 32 rows, y = wh (0..255).  256 threads / CTA.
// smem: Ksh[512][33] + Qsh[32][33]  (pitch 33 -> conflict-free strided reads)
// Each warp owns 4 rows; each lane owns cols {lane + 32j}, j=0..15 (64 acc).
// ---------------------------------------------------------------------------
__global__ __launch_bounds__(256, 2)
void qk_softmax_kernel(const float* __restrict__ qkv,
                       float* __restrict__ attn_out) {
    extern __shared__ float sm[];
    float* Ksh = sm;                  // 512*33
    float* Qsh = sm + 512 * 33;       // 32*33

    int wh = blockIdx.y;  int n = wh >> 3, h = wh & 7;
    int b  = n >> 3,      w2 = n & 7;
    int rb = blockIdx.x * 32;
    int tid = threadIdx.x, lane = tid & 31, warp = tid >> 5;

    const float* Kg = qkv + ((size_t)(4 + b)) * 4096 * 256;   // s=1
    const float* Qg = qkv + ((size_t)(0 + b)) * 4096 * 256;   // s=0

    // Load K[512][32] (vector gmem load, scalar smem store due to pitch 33)
    for (int i = tid; i < 512 * 8; i += 256) {
        int row = i >> 3, v4 = i & 7;
        int l = (row >> 3) * 64 + w2 * 8 + (row & 7);
        float4 val = *(const float4*)(Kg + (size_t)l * 256 + h * 32 + v4 * 4);
        float* dst = Ksh + row * 33 + v4 * 4;
        dst[0] = val.x; dst[1] = val.y; dst[2] = val.z; dst[3] = val.w;
    }
    // Load Q tile [32][32], pre-scaled
    for (int i = tid; i < 32 * 8; i += 256) {
        int row = i >> 3, v4 = i & 7;
        int grow = rb + row;
        int l = (grow >> 3) * 64 + w2 * 8 + (grow & 7);
        float4 val = *(const float4*)(Qg + (size_t)l * 256 + h * 32 + v4 * 4);
        float* dst = Qsh + row * 33 + v4 * 4;
        dst[0] = val.x * SCALE; dst[1] = val.y * SCALE;
        dst[2] = val.z * SCALE; dst[3] = val.w * SCALE;
    }
    __syncthreads();

    float acc[4][16];
    #pragma unroll
    for (int rr = 0; rr < 4; rr++)
        #pragma unroll
        for (int j = 0; j < 16; j++) acc[rr][j] = 0.f;

    #pragma unroll 8
    for (int d = 0; d < 32; d++) {
        float q0 = Qsh[(warp * 4 + 0) * 33 + d];
        float q1 = Qsh[(warp * 4 + 1) * 33 + d];
        float q2 = Qsh[(warp * 4 + 2) * 33 + d];
        float q3 = Qsh[(warp * 4 + 3) * 33 + d];
        #pragma unroll
        for (int j = 0; j < 16; j++) {
            float kv = Ksh[(lane + 32 * j) * 33 + d];
            acc[0][j] += q0 * kv;
            acc[1][j] += q1 * kv;
            acc[2][j] += q2 * kv;
            acc[3][j] += q3 * kv;
        }
    }

    // Softmax per row (512 values spread 16 per lane), then write attn
    float* outp = attn_out + ((size_t)wh * 512) * 512;
    #pragma unroll
    for (int rr = 0; rr < 4; rr++) {
        int row = rb + warp * 4 + rr;
        float m = acc[rr][0];
        #pragma unroll
        for (int j = 1; j < 16; j++) m = fmaxf(m, acc[rr][j]);
        #pragma unroll
        for (int off = 16; off; off >>= 1)
            m = fmaxf(m, __shfl_xor_sync(0xffffffffu, m, off));
        float s = 0.f;
        #pragma unroll
        for (int j = 0; j < 16; j++) {
            float e = __expf(acc[rr][j] - m);
            acc[rr][j] = e; s += e;
        }
        #pragma unroll
        for (int off = 16; off; off >>= 1)
            s += __shfl_xor_sync(0xffffffffu, s, off);
        float inv = 1.0f / s;
        #pragma unroll
        for (int j = 0; j < 16; j++)
            outp[(size_t)row * 512 + 32 * j + lane] = acc[rr][j] * inv;
    }
}

// ---------------------------------------------------------------------------
// Kernel 3: O = P @ V + lepe, scatter to x[b, l, c].
// Grid: x = 4 row-blocks of 128 rows, y = wh.  256 threads / CTA.
// smem: Vsh[512][32] (float4-friendly) + Psh[128][65].
// Thread (ty=tid>>3, tx=tid&7): rows ty*4..+3, cols tx*4..+3 (4x4 reg tile).
// ---------------------------------------------------------------------------
__global__ __launch_bounds__(256, 2)
void pv_kernel(const float* __restrict__ qkv,
               const float* __restrict__ attn,
               float* __restrict__ xout) {
    extern __shared__ float sm[];
    float* Vsh = sm;                  // 512*32
    float* Psh = sm + 512 * 32;       // 128*65

    int wh = blockIdx.y;  int n = wh >> 3, h = wh & 7;
    int b  = n >> 3,      w2 = n & 7;
    int rb = blockIdx.x * 128;
    int tid = threadIdx.x;
    int ty = tid >> 3, tx = tid & 7;

    const float* Vg = qkv + ((size_t)(8 + b)) * 4096 * 256;   // s=2
    for (int i = tid; i < 512 * 8; i += 256) {
        int row = i >> 3, v4 = i & 7;
        int l = (row >> 3) * 64 + w2 * 8 + (row & 7);
        float4 val = *(const float4*)(Vg + (size_t)l * 256 + h * 32 + v4 * 4);
        *(float4*)(Vsh + row * 32 + v4 * 4) = val;
    }

    const float* Pg = attn + (size_t)wh * 512 * 512;
    float acc[4][4];
    #pragma unroll
    for (int rr = 0; rr < 4; rr++)
        #pragma unroll
        for (int cc = 0; cc < 4; cc++) acc[rr][cc] = 0.f;

    for (int kt = 0; kt < 8; kt++) {
        __syncthreads();   // covers V load (kt=0) and Psh reuse (kt>0)
        for (int i = tid; i < 128 * 16; i += 256) {
            int row = i >> 4, k4 = i & 15;
            float4 val = *(const float4*)(Pg + (size_t)(rb + row) * 512 + kt * 64 + k4 * 4);
            float* dst = Psh + row * 65 + k4 * 4;
            dst[0] = val.x; dst[1] = val.y; dst[2] = val.z; dst[3] = val.w;
        }
        __syncthreads();
        #pragma unroll 8
        for (int k = 0; k < 64; k++) {
            float4 vv = *(const float4*)(Vsh + (kt * 64 + k) * 32 + tx * 4);
            #pragma unroll
            for (int rr = 0; rr < 4; rr++) {
                float p = Psh[(ty * 4 + rr) * 65 + k];
                acc[rr][0] += p * vv.x;
                acc[rr][1] += p * vv.y;
                acc[rr][2] += p * vv.z;
                acc[rr][3] += p * vv.w;
            }
        }
    }

    // Epilogue: add lepe, scatter to token layout
    #pragma unroll
    for (int rr = 0; rr < 4; rr++) {
        int t  = rb + ty * 4 + rr;
        int hs = t >> 3, ws = t & 7;
        int l  = hs * 64 + w2 * 8 + ws;
        int c0 = h * 32 + tx * 4;
        float4 le = *(const float4*)(g_lepe + ((size_t)n * 512 + t) * 256 + c0);
        float4 o;
        o.x = acc[rr][0] + le.x;
        o.y = acc[rr][1] + le.y;
        o.z = acc[rr][2] + le.z;
        o.w = acc[rr][3] + le.w;
        *(float4*)(xout + ((size_t)b * 4096 + l) * 256 + c0) = o;
    }
}

// ---------------------------------------------------------------------------
extern "C" void kernel_launch(void* const* d_in, const int* in_sizes, int n_in,
                              void* d_out, int out_size) {
    const float* qkv = (const float*)d_in[0];
    const float* cw  = (const float*)d_in[1];
    const float* cb  = (const float*)d_in[2];
    float* xout = (float*)d_out;
    float* attn = xout + (size_t)4 * 4096 * 256;    // x first, then attn

    const int SMEM_A = (512 * 33 + 32 * 33) * 4;    // 71808
    const int SMEM_B = (512 * 32 + 128 * 65) * 4;   // 98816
    cudaFuncSetAttribute(qk_softmax_kernel,
                         cudaFuncAttributeMaxDynamicSharedMemorySize, SMEM_A);
    cudaFuncSetAttribute(pv_kernel,
                         cudaFuncAttributeMaxDynamicSharedMemorySize, SMEM_B);

    lepe_kernel<<<NWB * WIN, 256>>>(qkv, cw, cb);
    qk_softmax_kernel<<<dim3(16, 256), 256, SMEM_A>>>(qkv, attn);
    pv_kernel<<<dim3(4, 256), 256, SMEM_B>>>(qkv, attn, xout);
}

// round 3
// speedup vs baseline: 1.1722x; 1.1722x over previous
#include <cuda_runtime.h>

#define SCALE 0.17677669529663687f     // 32^-0.5

typedef unsigned long long ull;

// Packed dual-fp32 FMA (sm_100+): acc(2xf32) += a(2xf32) * b(2xf32)
#define FMA2(acc, a, b) \
    asm("fma.rn.f32x2 %0, %1, %2, %0;" : "+l"(acc) : "l"(a), "l"(b))

// ---------------------------------------------------------------------------
// Kernel 1: S = scale*Q K^T per (window,head), row softmax, write attn.
// Grid (16, 256), 256 threads. Warp owns 4 rows; lane owns 8 col-PAIRS at
// cols {2*lane + 64*p}. FFMA2 packs over the column pair.
// smem: Kt[32][512] (d-major transposed K) + Qd[32][68] (duplicated (q,q)).
// ---------------------------------------------------------------------------
__global__ __launch_bounds__(256, 2)
void qk_softmax_kernel(const float* __restrict__ qkv,
                       float* __restrict__ attn_out) {
    extern __shared__ float sm[];
    float* Kt = sm;                 // [32][512]: Kt[d*512 + col] = K[col][d]
    float* Qd = sm + 32 * 512;      // [32][68]:  (q,q) dup pairs, pitch 68

    int wh = blockIdx.y;  int n = wh >> 3, h = wh & 7;
    int b  = n >> 3,      w2 = n & 7;
    int rb = blockIdx.x * 32;
    int tid = threadIdx.x, lane = tid & 31, warp = tid >> 5;

    const float* Kg = qkv + (size_t)(4 + b) * 4096 * 256;   // s=1
    const float* Qg = qkv + (size_t)(0 + b) * 4096 * 256;   // s=0

    // Fill Kt transposed: one thread per column (conflict-free STS)
    for (int c = tid; c < 512; c += 256) {
        int l = (c >> 3) * 64 + w2 * 8 + (c & 7);
        const float4* src = (const float4*)(Kg + (size_t)l * 256 + h * 32);
        #pragma unroll
        for (int v4 = 0; v4 < 8; v4++) {
            float4 val = src[v4];
            Kt[(4 * v4 + 0) * 512 + c] = val.x;
            Kt[(4 * v4 + 1) * 512 + c] = val.y;
            Kt[(4 * v4 + 2) * 512 + c] = val.z;
            Kt[(4 * v4 + 3) * 512 + c] = val.w;
        }
    }
    // Fill Qd duplicated pairs (pre-scaled)
    for (int i = tid; i < 32 * 32; i += 256) {
        int row = i >> 5, d = i & 31;
        int grow = rb + row;
        int l = (grow >> 3) * 64 + w2 * 8 + (grow & 7);
        float q = Qg[(size_t)l * 256 + h * 32 + d] * SCALE;
        *(float2*)(Qd + row * 68 + 2 * d) = make_float2(q, q);
    }
    __syncthreads();

    ull acc[4][8];
    #pragma unroll
    for (int r = 0; r < 4; r++)
        #pragma unroll
        for (int p = 0; p < 8; p++) acc[r][p] = 0ull;

    const float* Ktb = Kt + 2 * lane;
    const float* Qb  = Qd + (warp * 4) * 68;

    #pragma unroll 4
    for (int d = 0; d < 32; d += 2) {
        // q pairs for d and d+1, 4 rows (LDS.128 broadcast, 16B aligned)
        ulonglong2 q0 = *(const ulonglong2*)(Qb + 0 * 68 + 2 * d);
        ulonglong2 q1 = *(const ulonglong2*)(Qb + 1 * 68 + 2 * d);
        ulonglong2 q2 = *(const ulonglong2*)(Qb + 2 * 68 + 2 * d);
        ulonglong2 q3 = *(const ulonglong2*)(Qb + 3 * 68 + 2 * d);
        #pragma unroll
        for (int p = 0; p < 8; p++) {
            ull kv0 = *(const ull*)(Ktb + d * 512 + 64 * p);
            FMA2(acc[0][p], kv0, q0.x);
            FMA2(acc[1][p], kv0, q1.x);
            FMA2(acc[2][p], kv0, q2.x);
            FMA2(acc[3][p], kv0, q3.x);
            ull kv1 = *(const ull*)(Ktb + (d + 1) * 512 + 64 * p);
            FMA2(acc[0][p], kv1, q0.y);
            FMA2(acc[1][p], kv1, q1.y);
            FMA2(acc[2][p], kv1, q2.y);
            FMA2(acc[3][p], kv1, q3.y);
        }
    }

    // Softmax per row, write attn (coalesced float2 stores)
    float* outp = attn_out + (size_t)wh * 512 * 512;
    #pragma unroll
    for (int rr = 0; rr < 4; rr++) {
        float v[16];
        #pragma unroll
        for (int p = 0; p < 8; p++) {
            float2 f = *(float2*)&acc[rr][p];
            v[2 * p] = f.x; v[2 * p + 1] = f.y;
        }
        float m = v[0];
        #pragma unroll
        for (int j = 1; j < 16; j++) m = fmaxf(m, v[j]);
        #pragma unroll
        for (int off = 16; off; off >>= 1)
            m = fmaxf(m, __shfl_xor_sync(0xffffffffu, m, off));
        float ssum = 0.f;
        #pragma unroll
        for (int j = 0; j < 16; j++) {
            float e = __expf(v[j] - m);
            v[j] = e; ssum += e;
        }
        #pragma unroll
        for (int off = 16; off; off >>= 1)
            ssum += __shfl_xor_sync(0xffffffffu, ssum, off);
        float inv = 1.0f / ssum;
        float* orow = outp + (size_t)(rb + warp * 4 + rr) * 512 + 2 * lane;
        #pragma unroll
        for (int p = 0; p < 8; p++)
            *(float2*)(orow + 64 * p) = make_float2(v[2 * p] * inv, v[2 * p + 1] * inv);
    }
}

// ---------------------------------------------------------------------------
// Kernel 2: O = P @ V + LePE(conv3x3 on V window), scatter to x[b, l, c].
// Grid (2, 256), 256 threads, CTA tile 256 rows x 32 cols.
// Thread (ty=tid>>3, tx=tid&7): 8 rows x 4 cols, FFMA2 packed over k-pairs.
//
// Pairing contract (step a processes ACTUAL k-pair g = kt*16 + a):
//   V fill stores pair g of channel c at slot g ^ s,  s = (c>>4)&1
//     -> consumer reads slot kt*16 + (a^s)
//   P fill stores pair g of row r at offset 2*(g ^ r2), r2 = (r>>4)&1
//     (= swap the two float2 halves of each float4 when r2)
//     -> consumer reads offset 2*(a^r2), r2 = (ty>>1)&1 (uniform per thread)
// Both XORs break the ty/ty+2 and tx/tx+4 bank collisions -> conflict-free.
// LePE conv fused into epilogue: neighbor token k' = t + 8*dy + dx is a row
// of the SAME V window already resident in Vt.
// ---------------------------------------------------------------------------
__global__ __launch_bounds__(256, 2)
void pv_kernel(const float* __restrict__ qkv,
               const float* __restrict__ attn,
               const float* __restrict__ cw,
               const float* __restrict__ cb,
               float* __restrict__ xout) {
    extern __shared__ float sm[];
    float* Vt  = sm;                     // [32][514]
    float* Psh = sm + 32 * 514;          // [256][34]
    float* Wsh = Psh + 256 * 34;         // [32*9]
    float* Bsh = Wsh + 288;              // [32]

    int wh = blockIdx.y;  int n = wh >> 3, h = wh & 7;
    int b  = n >> 3,      w2 = n & 7;
    int rb = blockIdx.x * 256;
    int tid = threadIdx.x;
    int tx = tid & 7, ty = tid >> 3;
    int c0 = tx * 4;
    int s  = (tx >> 2) & 1;              // == ((c0+cc)>>4)&1 for cc in 0..3
    int r2 = (ty >> 1) & 1;              // == ((ty*8+rr)>>4)&1 for rr in 0..7

    const float* Vg = qkv + (size_t)(8 + b) * 4096 * 256;   // s=2
    {   // Fill Vt transposed + swizzled (conflict-free thanks to sc XOR)
        int c = tid & 31;
        int sc = (c >> 4) & 1;
        for (int k = tid >> 5; k < 512; k += 8) {
            int l = (k >> 3) * 64 + w2 * 8 + (k & 7);
            Vt[c * 514 + 2 * ((k >> 1) ^ sc) + (k & 1)] =
                Vg[(size_t)l * 256 + h * 32 + c];
        }
    }
    for (int i = tid; i < 288; i += 256) Wsh[i] = cw[(h * 32) * 9 + i];
    if (tid < 32) Bsh[tid] = cb[h * 32 + tid];

    const float* Pg = attn + (size_t)wh * 512 * 512 + (size_t)rb * 512;
    ull acc[8][4];
    #pragma unroll
    for (int r = 0; r < 8; r++)
        #pragma unroll
        for (int c = 0; c < 4; c++) acc[r][c] = 0ull;

    const float* Pb = Psh + (ty * 8) * 34;
    const float* Vb = Vt + c0 * 514;

    for (int kt = 0; kt < 16; kt++) {
        __syncthreads();                      // kt=0 also covers Vt/W fill
        #pragma unroll
        for (int it = 0; it < 8; it++) {
            int i = tid + it * 256;
            int row = i >> 3, kk = i & 7;
            int rw = (row >> 4) & 1;          // row-group swizzle bit
            float4 v = *(const float4*)(Pg + (size_t)row * 512 + kt * 32 + kk * 4);
            float2* dst = (float2*)(Psh + row * 34 + kk * 4);
            dst[rw]     = make_float2(v.x, v.y);   // pair 2kk   -> off 2*(2kk^rw)
            dst[rw ^ 1] = make_float2(v.z, v.w);   // pair 2kk+1 -> off 2*((2kk+1)^rw)
        }
        __syncthreads();
        #pragma unroll 4
        for (int a = 0; a < 16; a++) {
            // actual k-pair g = kt*16 + a for every thread
            int vslot = kt * 16 + (a ^ s);
            ull vv0 = *(const ull*)(Vb + 0 * 514 + 2 * vslot);
            ull vv1 = *(const ull*)(Vb + 1 * 514 + 2 * vslot);
            ull vv2 = *(const ull*)(Vb + 2 * 514 + 2 * vslot);
            ull vv3 = *(const ull*)(Vb + 3 * 514 + 2 * vslot);
            int poff = 2 * (a ^ r2);
            #pragma unroll
            for (int rr = 0; rr < 8; rr++) {
                ull p = *(const ull*)(Pb + rr * 34 + poff);
                FMA2(acc[rr][0], p, vv0);
                FMA2(acc[rr][1], p, vv1);
                FMA2(acc[rr][2], p, vv2);
                FMA2(acc[rr][3], p, vv3);
            }
        }
    }

    // Epilogue: reduce packed halves, add fused LePE conv, float4 scatter.
    #pragma unroll
    for (int rr = 0; rr < 8; rr++) {
        int t  = rb + ty * 8 + rr;            // window token 0..511
        int hs = t >> 3, ws = t & 7;
        float4 res;
        float* rp = (float*)&res;
        #pragma unroll
        for (int cc = 0; cc < 4; cc++) {
            int c = c0 + cc;
            float2 f = *(float2*)&acc[rr][cc];
            float o = f.x + f.y + Bsh[c];
            #pragma unroll
            for (int dy = -1; dy <= 1; dy++) {
                if ((unsigned)(hs + dy) >= 64u) continue;
                #pragma unroll
                for (int dx = -1; dx <= 1; dx++) {
                    if ((unsigned)(ws + dx) >= 8u) continue;
                    int kk = t + dy * 8 + dx;
                    float vv = Vt[c * 514 + 2 * ((kk >> 1) ^ s) + (kk & 1)];
                    o += vv * Wsh[c * 9 + (dy + 1) * 3 + (dx + 1)];
                }
            }
            rp[cc] = o;
        }
        int l = hs * 64 + w2 * 8 + ws;
        *(float4*)(xout + ((size_t)b * 4096 + l) * 256 + h * 32 + c0) = res;
    }
}

// ---------------------------------------------------------------------------
extern "C" void kernel_launch(void* const* d_in, const int* in_sizes, int n_in,
                              void* d_out, int out_size) {
    const float* qkv = (const float*)d_in[0];
    const float* cw  = (const float*)d_in[1];
    const float* cb  = (const float*)d_in[2];
    float* xout = (float*)d_out;
    float* attn = xout + (size_t)4 * 4096 * 256;    // x first, then attn

    const int SMEM_A = (32 * 512 + 32 * 68) * 4;                 // 74240
    const int SMEM_B = (32 * 514 + 256 * 34 + 288 + 32) * 4;     // 101888
    cudaFuncSetAttribute(qk_softmax_kernel,
                         cudaFuncAttributeMaxDynamicSharedMemorySize, SMEM_A);
    cudaFuncSetAttribute(pv_kernel,
                         cudaFuncAttributeMaxDynamicSharedMemorySize, SMEM_B);

    qk_softmax_kernel<<<dim3(16, 256), 256, SMEM_A>>>(qkv, attn);
    pv_kernel<<<dim3(2, 256), 256, SMEM_B>>>(qkv, attn, cw, cb, xout);
}